// round 12
// baseline (speedup 1.0000x reference)
#include <cuda_runtime.h>
#include <cuda_fp16.h>
#include <cstdint>

#define ALPHA 0.2f
#define MAXN 50048

// ---------------- device scratch ----------------
__device__ float g_wself[128];
__device__ float g_wneigh[128];
__device__ float g_bufA[MAXN * 128];
__device__ float g_bufB[MAXN * 128];
__device__ float g_sum[384];
__device__ float g_sq[384];
__device__ __half g_bthi[3 * 16384];         // B^T hi per layer, [n][k]
__device__ __half g_btlo[3 * 16384];         // B^T lo

__device__ __forceinline__ float leaky(float x) { return fmaxf(x, ALPHA * x); }

// ---------------- prep_all: one launch for all preprocessing ----------------
__global__ void __launch_bounds__(256)
prep_all(const float* __restrict__ Wt, const float* __restrict__ W1,
         const float* __restrict__ W2, const float* __restrict__ W3,
         const float* __restrict__ a_att,
         __half* __restrict__ bthi, __half* __restrict__ btlo) {
    __shared__ float wrow[128];
    __shared__ float red1[8], red2[8];
    __shared__ float tile[32][33];
    int b = blockIdx.x;
    int tid = threadIdx.x;

    if (b < 128) {
        if (tid < 128) wrow[tid] = Wt[b * 128 + tid];
        if (b == 0 && tid < 128) {
            g_sum[tid] = 0.f; g_sum[tid + 128] = 0.f; g_sum[tid + 256] = 0.f;
            g_sq[tid] = 0.f;  g_sq[tid + 128] = 0.f;  g_sq[tid + 256] = 0.f;
        }
        __syncthreads();
        float v1 = 0.f, v2 = 0.f;
        if (tid < 128) {
            v1 = wrow[tid] * a_att[tid];
            v2 = wrow[tid] * a_att[128 + tid];
        }
#pragma unroll
        for (int o = 16; o > 0; o >>= 1) {
            v1 += __shfl_xor_sync(0xffffffffu, v1, o);
            v2 += __shfl_xor_sync(0xffffffffu, v2, o);
        }
        if ((tid & 31) == 0) { red1[tid >> 5] = v1; red2[tid >> 5] = v2; }
        __syncthreads();
        if (tid == 0) {
            g_wself[b] = red1[0] + red1[1] + red1[2] + red1[3];
            g_wneigh[b] = red2[0] + red2[1] + red2[2] + red2[3];
        }
        if (tid < 128) {
            float acc = 0.f;
#pragma unroll 8
            for (int t = 0; t < 128; t++) acc += wrow[t] * W1[t * 128 + tid];
            __half h = __float2half_rn(acc);
            bthi[tid * 128 + b] = h;
            btlo[tid * 128 + b] = __float2half_rn(acc - __half2float(h));
        }
    } else {
        int layer = b - 127;  // 1 or 2
        const float* W = (layer == 1) ? W2 : W3;
        __half* oh = bthi + layer * 16384;
        __half* ol = btlo + layer * 16384;
        int tx = tid & 31, ty = tid >> 5;
        for (int ti = 0; ti < 4; ti++)
            for (int tj = 0; tj < 4; tj++) {
                __syncthreads();
#pragma unroll
                for (int it = 0; it < 4; it++)
                    tile[ty + 8 * it][tx] = W[(ti * 32 + ty + 8 * it) * 128 + tj * 32 + tx];
                __syncthreads();
#pragma unroll
                for (int it = 0; it < 4; it++) {
                    int n = tj * 32 + ty + 8 * it, k = ti * 32 + tx;
                    float v = tile[tx][ty + 8 * it];
                    __half h = __float2half_rn(v);
                    oh[n * 128 + k] = h;
                    ol[n * 128 + k] = __float2half_rn(v - __half2float(h));
                }
            }
    }
}

// ---------------- shared GEMM pieces ----------------
#define A_STRIDE 272
#define SM_BIAS 0
#define SM_CSUM 512
#define SM_CSQ  1024
#define SM_AIN  1536
#define SM_CIN  2048
#define SM_AH   2560
#define SM_BHI  (SM_AH + 128 * A_STRIDE)
#define SM_BLO  (SM_BHI + 128 * A_STRIDE)
#define SM_TOTAL (SM_BLO + 128 * A_STRIDE)

__device__ __forceinline__ void mma16816(float* c, uint32_t a0, uint32_t a1, uint32_t a2,
                                         uint32_t a3, uint32_t b0, uint32_t b1) {
    asm volatile(
        "mma.sync.aligned.m16n8k16.row.col.f32.f16.f16.f32 "
        "{%0,%1,%2,%3}, {%4,%5,%6,%7}, {%8,%9}, {%0,%1,%2,%3};\n"
        : "+f"(c[0]), "+f"(c[1]), "+f"(c[2]), "+f"(c[3])
        : "r"(a0), "r"(a1), "r"(a2), "r"(a3), "r"(b0), "r"(b1));
}

// MMA mainloop + epilogue (identical for both kernels), expects panels staged.
__device__ __forceinline__ void gemm_core(char* smem, int tid, float* __restrict__ Y,
                                          float* __restrict__ psum, float* __restrict__ psq,
                                          int row0, int N) {
    int wid = tid >> 5, lane = tid & 31;
    int wm = wid >> 2, wn = wid & 3;
    int g = lane >> 2, t = lane & 3;

    float acc[4][4][4];
#pragma unroll
    for (int mt = 0; mt < 4; mt++)
#pragma unroll
        for (int nt = 0; nt < 4; nt++)
#pragma unroll
            for (int j = 0; j < 4; j++) acc[mt][nt][j] = 0.f;

    const int abase0 = (wm * 64 + g) * A_STRIDE + t * 4;
    const int bbase0 = (wn * 32 + g) * A_STRIDE + t * 4;

#pragma unroll 1
    for (int s = 0; s < 2; s++) {
        const char* Ap = smem + SM_AH + abase0;
        const char* Bp = smem + (s ? SM_BLO : SM_BHI) + bbase0;
#pragma unroll
        for (int ks = 0; ks < 8; ks++) {
            uint32_t a0[4], a1[4], a2[4], a3[4], b0[4], b1[4];
#pragma unroll
            for (int mt = 0; mt < 4; mt++) {
                const char* p = Ap + mt * 16 * A_STRIDE + ks * 32;
                a0[mt] = *(const uint32_t*)(p);
                a1[mt] = *(const uint32_t*)(p + 8 * A_STRIDE);
                a2[mt] = *(const uint32_t*)(p + 16);
                a3[mt] = *(const uint32_t*)(p + 8 * A_STRIDE + 16);
            }
#pragma unroll
            for (int nt = 0; nt < 4; nt++) {
                const char* p = Bp + nt * 8 * A_STRIDE + ks * 32;
                b0[nt] = *(const uint32_t*)(p);
                b1[nt] = *(const uint32_t*)(p + 16);
            }
#pragma unroll
            for (int mt = 0; mt < 4; mt++)
#pragma unroll
                for (int nt = 0; nt < 4; nt++)
                    mma16816(acc[mt][nt], a0[mt], a1[mt], a2[mt], a3[mt], b0[nt], b1[nt]);
        }
    }

    float scol[8], qcol[8];
#pragma unroll
    for (int j = 0; j < 8; j++) { scol[j] = 0.f; qcol[j] = 0.f; }

    const float* bs = (const float*)(smem + SM_BIAS);
#pragma unroll
    for (int nt = 0; nt < 4; nt++) {
        int col = wn * 32 + nt * 8 + 2 * t;
        float bv0 = bs[col], bv1 = bs[col + 1];
#pragma unroll
        for (int mt = 0; mt < 4; mt++) {
            int row = row0 + wm * 64 + mt * 16 + g;
            float c0 = acc[mt][nt][0] + bv0;
            float c1 = acc[mt][nt][1] + bv1;
            float c2 = acc[mt][nt][2] + bv0;
            float c3 = acc[mt][nt][3] + bv1;
            if (row < N) {
                *(float2*)(Y + (long)row * 128 + col) = make_float2(c0, c1);
                scol[nt * 2 + 0] += c0; qcol[nt * 2 + 0] += c0 * c0;
                scol[nt * 2 + 1] += c1; qcol[nt * 2 + 1] += c1 * c1;
            }
            if (row + 8 < N) {
                *(float2*)(Y + (long)(row + 8) * 128 + col) = make_float2(c2, c3);
                scol[nt * 2 + 0] += c2; qcol[nt * 2 + 0] += c2 * c2;
                scol[nt * 2 + 1] += c3; qcol[nt * 2 + 1] += c3 * c3;
            }
        }
    }
#pragma unroll
    for (int j = 0; j < 8; j++) {
#pragma unroll
        for (int o = 4; o < 32; o <<= 1) {
            scol[j] += __shfl_xor_sync(0xffffffffu, scol[j], o);
            qcol[j] += __shfl_xor_sync(0xffffffffu, qcol[j], o);
        }
    }
    if (g == 0) {
        float* cs = (float*)(smem + SM_CSUM);
        float* cq = (float*)(smem + SM_CSQ);
#pragma unroll
        for (int nt = 0; nt < 4; nt++) {
            int col = wn * 32 + nt * 8 + 2 * t;
            atomicAdd(&cs[col], scol[nt * 2 + 0]);
            atomicAdd(&cs[col + 1], scol[nt * 2 + 1]);
            atomicAdd(&cq[col], qcol[nt * 2 + 0]);
            atomicAdd(&cq[col + 1], qcol[nt * 2 + 1]);
        }
    }
    __syncthreads();
    if (tid < 128) {
        atomicAdd(&psum[tid], ((const float*)(smem + SM_CSUM))[tid]);
        atomicAdd(&psq[tid], ((const float*)(smem + SM_CSQ))[tid]);
    }
}

// ---------------- FUSED attention + GEMM1 ----------------
// B panels staged first (L2 loads overlap the neighbor stream); each of the 8
// warps runs chunked online-softmax attention for 16 nodes, writing fp16 x
// directly into the smem A panel; then straight into MMA + stats epilogue.
__global__ void __launch_bounds__(256, 2)
attn_gemm1(const float* __restrict__ selfv, const float* __restrict__ neigh,
           const float* __restrict__ eps_p,
           const __half* __restrict__ bthi, const __half* __restrict__ btlo,
           const float* __restrict__ bias,
           float* __restrict__ Y, float* __restrict__ psum, float* __restrict__ psq,
           int N) {
    extern __shared__ char smem[];
    int tid = threadIdx.x;
    int wid = tid >> 5, l = tid & 31;
    int row0 = blockIdx.x << 7;

    if (tid < 128) {
        ((float*)(smem + SM_BIAS))[tid] = bias[tid];
        ((float*)(smem + SM_CSUM))[tid] = 0.f;
        ((float*)(smem + SM_CSQ))[tid] = 0.f;
    }

    // B staging first: L2-resident, overlaps the DRAM neighbor stream below.
#pragma unroll
    for (int it = 0; it < 8; it++) {
        int fi = tid + (it << 8);
        int n = fi >> 4, c = fi & 15;
        uint4 vh = ((const uint4*)bthi)[fi];
        uint4 vl = ((const uint4*)btlo)[fi];
        int off = n * A_STRIDE + (c << 4);
        *(uint4*)(smem + SM_BHI + off) = vh;
        *(uint4*)(smem + SM_BLO + off) = vl;
    }

    float onepe = 1.0f + eps_p[0];
    float4 ws4 = ((const float4*)g_wself)[l];
    float4 wn4 = ((const float4*)g_wneigh)[l];

    // Attention: warp wid handles rows [wid*16, wid*16+16)
#pragma unroll 1
    for (int i = 0; i < 16; i++) {
        int r = wid * 16 + i;
        int n = row0 + r;
        int nn = (n < N) ? n : (N - 1);

        float4 sv = ((const float4*)(selfv + (long)nn * 128))[l];
        const float4* nb = (const float4*)(neigh + (long)nn * 3200);

        float ss = sv.x * ws4.x + sv.y * ws4.y + sv.z * ws4.z + sv.w * ws4.w;
#pragma unroll
        for (int o = 16; o > 0; o >>= 1) ss += __shfl_xor_sync(0xffffffffu, ss, o);

        float4 buf[2][5];
#pragma unroll
        for (int j = 0; j < 5; j++) buf[0][j] = nb[j * 32 + l];

        float m = -1e30f, Z = 0.f;
        float4 acc = make_float4(0.f, 0.f, 0.f, 0.f);

#pragma unroll
        for (int c = 0; c < 5; c++) {
            const int cur = c & 1, nxt = cur ^ 1;
            if (c < 4) {
#pragma unroll
                for (int j = 0; j < 5; j++) buf[nxt][j] = nb[(5 * (c + 1) + j) * 32 + l];
            }
            float p[5];
#pragma unroll
            for (int j = 0; j < 5; j++) {
                float4 v = buf[cur][j];
                p[j] = v.x * wn4.x + v.y * wn4.y + v.z * wn4.z + v.w * wn4.w;
            }
#pragma unroll
            for (int o = 16; o > 0; o >>= 1)
#pragma unroll
                for (int j = 0; j < 5; j++) p[j] += __shfl_xor_sync(0xffffffffu, p[j], o);

            float mc = -1e30f;
#pragma unroll
            for (int j = 0; j < 5; j++) {
                p[j] = leaky(p[j] + ss);
                mc = fmaxf(mc, p[j]);
            }
            if (mc > m) {  // warp-uniform
                float sc = __expf(m - mc);
                Z *= sc;
                acc.x *= sc; acc.y *= sc; acc.z *= sc; acc.w *= sc;
                m = mc;
            }
#pragma unroll
            for (int j = 0; j < 5; j++) {
                float w = __expf(p[j] - m);
                Z += w;
                float4 v = buf[cur][j];
                acc.x += w * v.x; acc.y += w * v.y; acc.z += w * v.z; acc.w += w * v.w;
            }
        }

        float inv = 1.f / Z;
        __half2 h01 = __floats2half2_rn(onepe * sv.x + acc.x * inv,
                                        onepe * sv.y + acc.y * inv);
        __half2 h23 = __floats2half2_rn(onepe * sv.z + acc.z * inv,
                                        onepe * sv.w + acc.w * inv);
        int off = r * A_STRIDE + (l << 3);
        *(__half2*)(smem + SM_AH + off) = h01;
        *(__half2*)(smem + SM_AH + off + 4) = h23;
    }
    __syncthreads();

    gemm_core(smem, tid, Y, psum, psq, row0, N);
}

// ---------------- mma.sync GEMM layers 2/3: fp32 in + inline BN finalize ----------
__global__ void __launch_bounds__(256, 2)
gemm_mma(const float* __restrict__ X, const __half* __restrict__ bthi,
         const __half* __restrict__ btlo, const float* __restrict__ bias,
         const float* __restrict__ prev_sum, const float* __restrict__ prev_sq,
         const float* __restrict__ gam, const float* __restrict__ bet,
         float* __restrict__ Y, float* __restrict__ psum, float* __restrict__ psq,
         int N) {
    extern __shared__ char smem[];
    int tid = threadIdx.x;
    int row0 = blockIdx.x << 7;

    if (tid < 128) {
        ((float*)(smem + SM_BIAS))[tid] = bias[tid];
        ((float*)(smem + SM_CSUM))[tid] = 0.f;
        ((float*)(smem + SM_CSQ))[tid] = 0.f;
        float invN = 1.0f / (float)N;
        float mean = prev_sum[tid] * invN;
        float var = fmaxf(prev_sq[tid] * invN - mean * mean, 0.f);
        float a_ = gam[tid] * rsqrtf(var + 1e-5f);
        ((float*)(smem + SM_AIN))[tid] = a_;
        ((float*)(smem + SM_CIN))[tid] = bet[tid] - a_ * mean;
    }
    __syncthreads();

    const float* ainS = (const float*)(smem + SM_AIN);
    const float* cinS = (const float*)(smem + SM_CIN);
#pragma unroll
    for (int it = 0; it < 16; it++) {
        int fi = tid + (it << 8);
        int r = fi >> 5, q = fi & 31;
        int gr = row0 + r;
        float4 v = make_float4(0.f, 0.f, 0.f, 0.f);
        if (gr < N) v = ((const float4*)X)[gr * 32 + q];
        int kk = q << 2;
        float tt;
        tt = ainS[kk + 0] * v.x + cinS[kk + 0]; v.x = leaky(tt);
        tt = ainS[kk + 1] * v.y + cinS[kk + 1]; v.y = leaky(tt);
        tt = ainS[kk + 2] * v.z + cinS[kk + 2]; v.z = leaky(tt);
        tt = ainS[kk + 3] * v.w + cinS[kk + 3]; v.w = leaky(tt);
        __half2 h01 = __floats2half2_rn(v.x, v.y);
        __half2 h23 = __floats2half2_rn(v.z, v.w);
        int off = r * A_STRIDE + (q << 3);
        *(__half2*)(smem + SM_AH + off) = h01;
        *(__half2*)(smem + SM_AH + off + 4) = h23;
    }

#pragma unroll
    for (int it = 0; it < 8; it++) {
        int fi = tid + (it << 8);
        int n = fi >> 4, c = fi & 15;
        uint4 vh = ((const uint4*)bthi)[fi];
        uint4 vl = ((const uint4*)btlo)[fi];
        int off = n * A_STRIDE + (c << 4);
        *(uint4*)(smem + SM_BHI + off) = vh;
        *(uint4*)(smem + SM_BLO + off) = vl;
    }
    __syncthreads();

    gemm_core(smem, tid, Y, psum, psq, row0, N);
}

// ---------------- final BN + leaky (inline finalize, in place) ----------------
__global__ void epilogue_kernel(float* __restrict__ Y, const float* __restrict__ s,
                                const float* __restrict__ q, const float* __restrict__ gam,
                                const float* __restrict__ bet, int n4, float invN) {
    int i = blockIdx.x * blockDim.x + threadIdx.x;
    if (i < n4) {
        float4 v = ((const float4*)Y)[i];
        int cb = (i & 31) << 2;
        float o[4] = {v.x, v.y, v.z, v.w};
#pragma unroll
        for (int j = 0; j < 4; j++) {
            float mean = s[cb + j] * invN;
            float var = fmaxf(q[cb + j] * invN - mean * mean, 0.f);
            float a_ = gam[cb + j] * rsqrtf(var + 1e-5f);
            float c_ = bet[cb + j] - a_ * mean;
            o[j] = leaky(a_ * o[j] + c_);
        }
        ((float4*)Y)[i] = make_float4(o[0], o[1], o[2], o[3]);
    }
}

// ---------------- launch ----------------
extern "C" void kernel_launch(void* const* d_in, const int* in_sizes, int n_in,
                              void* d_out, int out_size) {
    const float* selfv = (const float*)d_in[0];
    const float* neigh = (const float*)d_in[1];
    const float* Wt    = (const float*)d_in[2];
    const float* aatt  = (const float*)d_in[3];
    const float* eps   = (const float*)d_in[4];
    const float* W1 = (const float*)d_in[5];
    const float* b1 = (const float*)d_in[6];
    const float* g1 = (const float*)d_in[7];
    const float* be1 = (const float*)d_in[8];
    const float* W2 = (const float*)d_in[9];
    const float* b2 = (const float*)d_in[10];
    const float* g2 = (const float*)d_in[11];
    const float* be2 = (const float*)d_in[12];
    const float* W3 = (const float*)d_in[13];
    const float* b3 = (const float*)d_in[14];
    const float* g3 = (const float*)d_in[15];
    const float* be3 = (const float*)d_in[16];
    float* out = (float*)d_out;

    int N = in_sizes[0] / 128;

    float *bufA = nullptr, *bufB = nullptr, *sum = nullptr, *sq = nullptr;
    __half *bthi = nullptr, *btlo = nullptr;
    cudaGetSymbolAddress((void**)&bufA, g_bufA);
    cudaGetSymbolAddress((void**)&bufB, g_bufB);
    cudaGetSymbolAddress((void**)&sum, g_sum);
    cudaGetSymbolAddress((void**)&sq, g_sq);
    cudaGetSymbolAddress((void**)&bthi, g_bthi);
    cudaGetSymbolAddress((void**)&btlo, g_btlo);

    cudaFuncSetAttribute(attn_gemm1, cudaFuncAttributeMaxDynamicSharedMemorySize, SM_TOTAL);
    cudaFuncSetAttribute(gemm_mma, cudaFuncAttributeMaxDynamicSharedMemorySize, SM_TOTAL);

    prep_all<<<130, 256>>>(Wt, W1, W2, W3, aatt, bthi, btlo);

    int gg = (N + 127) / 128;
    attn_gemm1<<<gg, 256, SM_TOTAL>>>(selfv, neigh, eps, bthi, btlo, b1,
                                      bufB, sum + 0, sq + 0, N);
    gemm_mma<<<gg, 256, SM_TOTAL>>>(bufB, bthi + 16384, btlo + 16384, b2,
                                    sum + 0, sq + 0, g1, be1,
                                    bufA, sum + 128, sq + 128, N);
    gemm_mma<<<gg, 256, SM_TOTAL>>>(bufA, bthi + 2 * 16384, btlo + 2 * 16384, b3,
                                    sum + 128, sq + 128, g2, be2,
                                    out, sum + 256, sq + 256, N);

    int n4 = N * 32;
    epilogue_kernel<<<(n4 + 255) / 256, 256>>>(out, sum + 256, sq + 256, g3, be3,
                                               n4, 1.0f / (float)N);
}

// round 13
// speedup vs baseline: 1.1022x; 1.1022x over previous
#include <cuda_runtime.h>
#include <cuda_fp16.h>
#include <cstdint>

#define ALPHA 0.2f
#define MAXN 50048

// ---------------- device scratch ----------------
__device__ float g_wself[128];
__device__ float g_wneigh[128];
__device__ __half g_bufH[MAXN * 128];        // attention output (fp16)
__device__ float g_bufA[MAXN * 128];
__device__ float g_bufB[MAXN * 128];
__device__ float g_sum[384];
__device__ float g_sq[384];
__device__ __half g_bthi[3 * 16384];         // B^T hi per layer, [n][k]
__device__ __half g_btlo[3 * 16384];         // B^T lo

__device__ __forceinline__ float leaky(float x) { return fmaxf(x, ALPHA * x); }

// ---------------- prep_all: one launch for all preprocessing ----------------
__global__ void __launch_bounds__(256)
prep_all(const float* __restrict__ Wt, const float* __restrict__ W1,
         const float* __restrict__ W2, const float* __restrict__ W3,
         const float* __restrict__ a_att,
         __half* __restrict__ bthi, __half* __restrict__ btlo) {
    __shared__ float wrow[128];
    __shared__ float red1[8], red2[8];
    __shared__ float tile[32][33];
    int b = blockIdx.x;
    int tid = threadIdx.x;

    if (b < 128) {
        if (tid < 128) wrow[tid] = Wt[b * 128 + tid];
        if (b == 0 && tid < 128) {
            g_sum[tid] = 0.f; g_sum[tid + 128] = 0.f; g_sum[tid + 256] = 0.f;
            g_sq[tid] = 0.f;  g_sq[tid + 128] = 0.f;  g_sq[tid + 256] = 0.f;
        }
        __syncthreads();
        float v1 = 0.f, v2 = 0.f;
        if (tid < 128) {
            v1 = wrow[tid] * a_att[tid];
            v2 = wrow[tid] * a_att[128 + tid];
        }
#pragma unroll
        for (int o = 16; o > 0; o >>= 1) {
            v1 += __shfl_xor_sync(0xffffffffu, v1, o);
            v2 += __shfl_xor_sync(0xffffffffu, v2, o);
        }
        if ((tid & 31) == 0) { red1[tid >> 5] = v1; red2[tid >> 5] = v2; }
        __syncthreads();
        if (tid == 0) {
            g_wself[b] = red1[0] + red1[1] + red1[2] + red1[3];
            g_wneigh[b] = red2[0] + red2[1] + red2[2] + red2[3];
        }
        if (tid < 128) {
            float acc = 0.f;
#pragma unroll 8
            for (int t = 0; t < 128; t++) acc += wrow[t] * W1[t * 128 + tid];
            __half h = __float2half_rn(acc);
            bthi[tid * 128 + b] = h;
            btlo[tid * 128 + b] = __float2half_rn(acc - __half2float(h));
        }
    } else {
        int layer = b - 127;  // 1 or 2
        const float* W = (layer == 1) ? W2 : W3;
        __half* oh = bthi + layer * 16384;
        __half* ol = btlo + layer * 16384;
        int tx = tid & 31, ty = tid >> 5;
        for (int ti = 0; ti < 4; ti++)
            for (int tj = 0; tj < 4; tj++) {
                __syncthreads();
#pragma unroll
                for (int it = 0; it < 4; it++)
                    tile[ty + 8 * it][tx] = W[(ti * 32 + ty + 8 * it) * 128 + tj * 32 + tx];
                __syncthreads();
#pragma unroll
                for (int it = 0; it < 4; it++) {
                    int n = tj * 32 + ty + 8 * it, k = ti * 32 + tx;
                    float v = tile[tx][ty + 8 * it];
                    __half h = __float2half_rn(v);
                    oh[n * 128 + k] = h;
                    ol[n * 128 + k] = __float2half_rn(v - __half2float(h));
                }
            }
    }
}

// ---------------- attention: chunked online softmax, double-buffered --------------
__global__ void __launch_bounds__(256, 3)
attn_kernel(const float* __restrict__ selfv, const float* __restrict__ neigh,
            const float* __restrict__ eps_p, __half* __restrict__ Xh, int N) {
    int tid = threadIdx.x;
    int wid = tid >> 5, l = tid & 31;
    int n = blockIdx.x * 8 + wid;
    int nn = (n < N) ? n : (N - 1);

    float onepe = 1.0f + eps_p[0];
    float4 ws4 = ((const float4*)g_wself)[l];
    float4 wn4 = ((const float4*)g_wneigh)[l];

    float4 sv = ((const float4*)(selfv + (long)nn * 128))[l];
    const float4* nb = (const float4*)(neigh + (long)nn * 3200);

    float ss = sv.x * ws4.x + sv.y * ws4.y + sv.z * ws4.z + sv.w * ws4.w;
#pragma unroll
    for (int o = 16; o > 0; o >>= 1) ss += __shfl_xor_sync(0xffffffffu, ss, o);

    float4 buf[2][5];
#pragma unroll
    for (int j = 0; j < 5; j++) buf[0][j] = nb[j * 32 + l];

    float m = -1e30f, Z = 0.f;
    float4 acc = make_float4(0.f, 0.f, 0.f, 0.f);

#pragma unroll
    for (int c = 0; c < 5; c++) {
        const int cur = c & 1, nxt = cur ^ 1;
        if (c < 4) {
#pragma unroll
            for (int j = 0; j < 5; j++) buf[nxt][j] = nb[(5 * (c + 1) + j) * 32 + l];
        }
        float p[5];
#pragma unroll
        for (int j = 0; j < 5; j++) {
            float4 v = buf[cur][j];
            p[j] = v.x * wn4.x + v.y * wn4.y + v.z * wn4.z + v.w * wn4.w;
        }
#pragma unroll
        for (int o = 16; o > 0; o >>= 1)
#pragma unroll
            for (int j = 0; j < 5; j++) p[j] += __shfl_xor_sync(0xffffffffu, p[j], o);

        float mc = -1e30f;
#pragma unroll
        for (int j = 0; j < 5; j++) {
            p[j] = leaky(p[j] + ss);
            mc = fmaxf(mc, p[j]);
        }
        if (mc > m) {  // warp-uniform
            float sc = __expf(m - mc);
            Z *= sc;
            acc.x *= sc; acc.y *= sc; acc.z *= sc; acc.w *= sc;
            m = mc;
        }
#pragma unroll
        for (int j = 0; j < 5; j++) {
            float w = __expf(p[j] - m);
            Z += w;
            float4 v = buf[cur][j];
            acc.x += w * v.x; acc.y += w * v.y; acc.z += w * v.z; acc.w += w * v.w;
        }
    }

    float inv = 1.f / Z;
    float x0 = onepe * sv.x + acc.x * inv;
    float x1 = onepe * sv.y + acc.y * inv;
    float x2 = onepe * sv.z + acc.z * inv;
    float x3 = onepe * sv.w + acc.w * inv;
    if (n < N) {
        __half2* dst = (__half2*)(Xh + (long)n * 128);
        dst[2 * l] = __floats2half2_rn(x0, x1);
        dst[2 * l + 1] = __floats2half2_rn(x2, x3);
    }
}

// ---------------- mma.sync GEMM: fp16 merged hi/lo mainloop, 2 blocks/SM ----------
#define A_STRIDE 272
#define SM_BIAS 0
#define SM_CSUM 512
#define SM_CSQ  1024
#define SM_AH   1536
#define SM_BHI  (SM_AH + 128 * A_STRIDE)
#define SM_BLO  (SM_BHI + 128 * A_STRIDE)
#define SM_TOTAL (SM_BLO + 128 * A_STRIDE)

__device__ __forceinline__ void mma16816(float* c, uint32_t a0, uint32_t a1, uint32_t a2,
                                         uint32_t a3, uint32_t b0, uint32_t b1) {
    asm volatile(
        "mma.sync.aligned.m16n8k16.row.col.f32.f16.f16.f32 "
        "{%0,%1,%2,%3}, {%4,%5,%6,%7}, {%8,%9}, {%0,%1,%2,%3};\n"
        : "+f"(c[0]), "+f"(c[1]), "+f"(c[2]), "+f"(c[3])
        : "r"(a0), "r"(a1), "r"(a2), "r"(a3), "r"(b0), "r"(b1));
}

// Merged-pass MMA mainloop + stats epilogue; expects A/B panels staged.
__device__ __forceinline__ void gemm_core(char* smem, int tid, float* __restrict__ Y,
                                          float* __restrict__ psum, float* __restrict__ psq,
                                          int row0, int N) {
    int wid = tid >> 5, lane = tid & 31;
    int wm = wid >> 2, wn = wid & 3;
    int g = lane >> 2, t = lane & 3;

    float acc[4][4][4];
#pragma unroll
    for (int mt = 0; mt < 4; mt++)
#pragma unroll
        for (int nt = 0; nt < 4; nt++)
#pragma unroll
            for (int j = 0; j < 4; j++) acc[mt][nt][j] = 0.f;

    const char* Ap = smem + SM_AH + (wm * 64 + g) * A_STRIDE + t * 4;
    const char* Bh = smem + SM_BHI + (wn * 32 + g) * A_STRIDE + t * 4;
    const char* Bl = smem + SM_BLO + (wn * 32 + g) * A_STRIDE + t * 4;

    // Single ks loop: load A fragments ONCE, MMA against both B-hi and B-lo.
#pragma unroll
    for (int ks = 0; ks < 8; ks++) {
        uint32_t a0[4], a1[4], a2[4], a3[4];
        uint32_t bh0[4], bh1[4], bl0[4], bl1[4];
#pragma unroll
        for (int mt = 0; mt < 4; mt++) {
            const char* p = Ap + mt * 16 * A_STRIDE + ks * 32;
            a0[mt] = *(const uint32_t*)(p);
            a1[mt] = *(const uint32_t*)(p + 8 * A_STRIDE);
            a2[mt] = *(const uint32_t*)(p + 16);
            a3[mt] = *(const uint32_t*)(p + 8 * A_STRIDE + 16);
        }
#pragma unroll
        for (int nt = 0; nt < 4; nt++) {
            const char* ph = Bh + nt * 8 * A_STRIDE + ks * 32;
            const char* pl = Bl + nt * 8 * A_STRIDE + ks * 32;
            bh0[nt] = *(const uint32_t*)(ph);
            bh1[nt] = *(const uint32_t*)(ph + 16);
            bl0[nt] = *(const uint32_t*)(pl);
            bl1[nt] = *(const uint32_t*)(pl + 16);
        }
#pragma unroll
        for (int mt = 0; mt < 4; mt++)
#pragma unroll
            for (int nt = 0; nt < 4; nt++) {
                mma16816(acc[mt][nt], a0[mt], a1[mt], a2[mt], a3[mt], bh0[nt], bh1[nt]);
                mma16816(acc[mt][nt], a0[mt], a1[mt], a2[mt], a3[mt], bl0[nt], bl1[nt]);
            }
    }

    float scol[8], qcol[8];
#pragma unroll
    for (int j = 0; j < 8; j++) { scol[j] = 0.f; qcol[j] = 0.f; }

    const float* bs = (const float*)(smem + SM_BIAS);
#pragma unroll
    for (int nt = 0; nt < 4; nt++) {
        int col = wn * 32 + nt * 8 + 2 * t;
        float bv0 = bs[col], bv1 = bs[col + 1];
#pragma unroll
        for (int mt = 0; mt < 4; mt++) {
            int row = row0 + wm * 64 + mt * 16 + g;
            float c0 = acc[mt][nt][0] + bv0;
            float c1 = acc[mt][nt][1] + bv1;
            float c2 = acc[mt][nt][2] + bv0;
            float c3 = acc[mt][nt][3] + bv1;
            if (row < N) {
                *(float2*)(Y + (long)row * 128 + col) = make_float2(c0, c1);
                scol[nt * 2 + 0] += c0; qcol[nt * 2 + 0] += c0 * c0;
                scol[nt * 2 + 1] += c1; qcol[nt * 2 + 1] += c1 * c1;
            }
            if (row + 8 < N) {
                *(float2*)(Y + (long)(row + 8) * 128 + col) = make_float2(c2, c3);
                scol[nt * 2 + 0] += c2; qcol[nt * 2 + 0] += c2 * c2;
                scol[nt * 2 + 1] += c3; qcol[nt * 2 + 1] += c3 * c3;
            }
        }
    }
#pragma unroll
    for (int j = 0; j < 8; j++) {
#pragma unroll
        for (int o = 4; o < 32; o <<= 1) {
            scol[j] += __shfl_xor_sync(0xffffffffu, scol[j], o);
            qcol[j] += __shfl_xor_sync(0xffffffffu, qcol[j], o);
        }
    }
    if (g == 0) {
        float* cs = (float*)(smem + SM_CSUM);
        float* cq = (float*)(smem + SM_CSQ);
#pragma unroll
        for (int nt = 0; nt < 4; nt++) {
            int col = wn * 32 + nt * 8 + 2 * t;
            atomicAdd(&cs[col], scol[nt * 2 + 0]);
            atomicAdd(&cs[col + 1], scol[nt * 2 + 1]);
            atomicAdd(&cq[col], qcol[nt * 2 + 0]);
            atomicAdd(&cq[col + 1], qcol[nt * 2 + 1]);
        }
    }
    __syncthreads();
    if (tid < 128) {
        atomicAdd(&psum[tid], ((const float*)(smem + SM_CSUM))[tid]);
        atomicAdd(&psq[tid], ((const float*)(smem + SM_CSQ))[tid]);
    }
}

// IN_HALF=true: X is fp16 (attention output), no input BN.
// IN_HALF=false: X is fp32 pre-BN; each thread computes its 4 BN coeffs in
// registers (q = tid&31 is constant across its staging rows) -> NO barrier
// before A staging; A DRAM loads issue from cycle ~0.
template <bool IN_HALF>
__global__ void __launch_bounds__(256, 2)
gemm_mma(const void* __restrict__ Xv, const __half* __restrict__ bthi,
         const __half* __restrict__ btlo, const float* __restrict__ bias,
         const float* __restrict__ prev_sum, const float* __restrict__ prev_sq,
         const float* __restrict__ gam, const float* __restrict__ bet,
         float* __restrict__ Y, float* __restrict__ psum, float* __restrict__ psq,
         int N) {
    extern __shared__ char smem[];
    int tid = threadIdx.x;
    int row0 = blockIdx.x << 7;

    if (tid < 128) {
        ((float*)(smem + SM_BIAS))[tid] = bias[tid];
        ((float*)(smem + SM_CSUM))[tid] = 0.f;
        ((float*)(smem + SM_CSQ))[tid] = 0.f;
    }

    // ---- stage A (no barrier needed before this) ----
    if (IN_HALF) {
        const __half* Xh = (const __half*)Xv;
#pragma unroll
        for (int it = 0; it < 16; it++) {
            int fi = tid + (it << 8);
            int r = fi >> 5, q = fi & 31;
            int gr = row0 + r;
            uint2 d = make_uint2(0u, 0u);
            if (gr < N) d = ((const uint2*)(Xh + (long)gr * 128))[q];
            int off = r * A_STRIDE + (q << 3);
            *(uint2*)(smem + SM_AH + off) = d;
        }
    } else {
        const float* X = (const float*)Xv;
        int q = tid & 31;
        int kk = q << 2;
        float invN = 1.0f / (float)N;
        float ai[4], ci[4];
#pragma unroll
        for (int j = 0; j < 4; j++) {
            float mean = prev_sum[kk + j] * invN;
            float var = fmaxf(prev_sq[kk + j] * invN - mean * mean, 0.f);
            float a_ = gam[kk + j] * rsqrtf(var + 1e-5f);
            ai[j] = a_;
            ci[j] = bet[kk + j] - a_ * mean;
        }
#pragma unroll
        for (int it = 0; it < 16; it++) {
            int fi = tid + (it << 8);
            int r = fi >> 5;
            int gr = row0 + r;
            float4 v = make_float4(0.f, 0.f, 0.f, 0.f);
            if (gr < N) v = ((const float4*)X)[gr * 32 + q];
            float tt;
            tt = ai[0] * v.x + ci[0]; v.x = leaky(tt);
            tt = ai[1] * v.y + ci[1]; v.y = leaky(tt);
            tt = ai[2] * v.z + ci[2]; v.z = leaky(tt);
            tt = ai[3] * v.w + ci[3]; v.w = leaky(tt);
            __half2 h01 = __floats2half2_rn(v.x, v.y);
            __half2 h23 = __floats2half2_rn(v.z, v.w);
            int off = r * A_STRIDE + (q << 3);
            *(__half2*)(smem + SM_AH + off) = h01;
            *(__half2*)(smem + SM_AH + off + 4) = h23;
        }
    }

    // ---- stage B: precomputed W^T hi/lo fp16 ----
#pragma unroll
    for (int it = 0; it < 8; it++) {
        int fi = tid + (it << 8);
        int n = fi >> 4, c = fi & 15;
        uint4 vh = ((const uint4*)bthi)[fi];
        uint4 vl = ((const uint4*)btlo)[fi];
        int off = n * A_STRIDE + (c << 4);
        *(uint4*)(smem + SM_BHI + off) = vh;
        *(uint4*)(smem + SM_BLO + off) = vl;
    }
    __syncthreads();

    gemm_core(smem, tid, Y, psum, psq, row0, N);
}

// ---------------- final BN + leaky (inline finalize, in place) ----------------
__global__ void epilogue_kernel(float* __restrict__ Y, const float* __restrict__ s,
                                const float* __restrict__ q, const float* __restrict__ gam,
                                const float* __restrict__ bet, int n4, float invN) {
    int i = blockIdx.x * blockDim.x + threadIdx.x;
    if (i < n4) {
        float4 v = ((const float4*)Y)[i];
        int cb = (i & 31) << 2;
        float o[4] = {v.x, v.y, v.z, v.w};
#pragma unroll
        for (int j = 0; j < 4; j++) {
            float mean = s[cb + j] * invN;
            float var = fmaxf(q[cb + j] * invN - mean * mean, 0.f);
            float a_ = gam[cb + j] * rsqrtf(var + 1e-5f);
            float c_ = bet[cb + j] - a_ * mean;
            o[j] = leaky(a_ * o[j] + c_);
        }
        ((float4*)Y)[i] = make_float4(o[0], o[1], o[2], o[3]);
    }
}

// ---------------- launch ----------------
extern "C" void kernel_launch(void* const* d_in, const int* in_sizes, int n_in,
                              void* d_out, int out_size) {
    const float* selfv = (const float*)d_in[0];
    const float* neigh = (const float*)d_in[1];
    const float* Wt    = (const float*)d_in[2];
    const float* aatt  = (const float*)d_in[3];
    const float* eps   = (const float*)d_in[4];
    const float* W1 = (const float*)d_in[5];
    const float* b1 = (const float*)d_in[6];
    const float* g1 = (const float*)d_in[7];
    const float* be1 = (const float*)d_in[8];
    const float* W2 = (const float*)d_in[9];
    const float* b2 = (const float*)d_in[10];
    const float* g2 = (const float*)d_in[11];
    const float* be2 = (const float*)d_in[12];
    const float* W3 = (const float*)d_in[13];
    const float* b3 = (const float*)d_in[14];
    const float* g3 = (const float*)d_in[15];
    const float* be3 = (const float*)d_in[16];
    float* out = (float*)d_out;

    int N = in_sizes[0] / 128;

    float *bufA = nullptr, *bufB = nullptr, *sum = nullptr, *sq = nullptr;
    __half *bufH = nullptr, *bthi = nullptr, *btlo = nullptr;
    cudaGetSymbolAddress((void**)&bufA, g_bufA);
    cudaGetSymbolAddress((void**)&bufB, g_bufB);
    cudaGetSymbolAddress((void**)&bufH, g_bufH);
    cudaGetSymbolAddress((void**)&sum, g_sum);
    cudaGetSymbolAddress((void**)&sq, g_sq);
    cudaGetSymbolAddress((void**)&bthi, g_bthi);
    cudaGetSymbolAddress((void**)&btlo, g_btlo);

    cudaFuncSetAttribute(gemm_mma<true>, cudaFuncAttributeMaxDynamicSharedMemorySize, SM_TOTAL);
    cudaFuncSetAttribute(gemm_mma<false>, cudaFuncAttributeMaxDynamicSharedMemorySize, SM_TOTAL);

    prep_all<<<130, 256>>>(Wt, W1, W2, W3, aatt, bthi, btlo);
    attn_kernel<<<(N + 7) / 8, 256>>>(selfv, neigh, eps, bufH, N);

    int gg = (N + 127) / 128;
    gemm_mma<true><<<gg, 256, SM_TOTAL>>>(bufH, bthi, btlo, b1,
                                          nullptr, nullptr, nullptr, nullptr,
                                          bufB, sum + 0, sq + 0, N);
    gemm_mma<false><<<gg, 256, SM_TOTAL>>>(bufB, bthi + 16384, btlo + 16384, b2,
                                           sum + 0, sq + 0, g1, be1,
                                           bufA, sum + 128, sq + 128, N);
    gemm_mma<false><<<gg, 256, SM_TOTAL>>>(bufA, bthi + 2 * 16384, btlo + 2 * 16384, b3,
                                           sum + 128, sq + 128, g2, be2,
                                           out, sum + 256, sq + 256, N);

    int n4 = N * 32;
    epilogue_kernel<<<(n4 + 255) / 256, 256>>>(out, sum + 256, sq + 256, g3, be3,
                                               n4, 1.0f / (float)N);
}

// round 14
// speedup vs baseline: 1.1696x; 1.0612x over previous
#include <cuda_runtime.h>
#include <cuda_fp16.h>
#include <cstdint>

#define ALPHA 0.2f
#define MAXN 50048

// ---------------- device scratch ----------------
__device__ float g_wself[128];
__device__ float g_wneigh[128];
__device__ __half g_bufH[MAXN * 128];        // attention output (fp16)
__device__ float g_bufA[MAXN * 128];
__device__ float g_bufB[MAXN * 128];
__device__ float g_sum[384];
__device__ float g_sq[384];
__device__ __half g_bthi[3 * 16384];         // B^T hi per layer, [n][k]
__device__ __half g_btlo[3 * 16384];         // B^T lo

__device__ __forceinline__ float leaky(float x) { return fmaxf(x, ALPHA * x); }

// ---------------- prep_all: one launch for all preprocessing ----------------
__global__ void __launch_bounds__(256)
prep_all(const float* __restrict__ Wt, const float* __restrict__ W1,
         const float* __restrict__ W2, const float* __restrict__ W3,
         const float* __restrict__ a_att,
         __half* __restrict__ bthi, __half* __restrict__ btlo) {
    __shared__ float wrow[128];
    __shared__ float red1[8], red2[8];
    __shared__ float tile[32][33];
    int b = blockIdx.x;
    int tid = threadIdx.x;

    if (b < 128) {
        if (tid < 128) wrow[tid] = Wt[b * 128 + tid];
        if (b == 0 && tid < 128) {
            g_sum[tid] = 0.f; g_sum[tid + 128] = 0.f; g_sum[tid + 256] = 0.f;
            g_sq[tid] = 0.f;  g_sq[tid + 128] = 0.f;  g_sq[tid + 256] = 0.f;
        }
        __syncthreads();
        float v1 = 0.f, v2 = 0.f;
        if (tid < 128) {
            v1 = wrow[tid] * a_att[tid];
            v2 = wrow[tid] * a_att[128 + tid];
        }
#pragma unroll
        for (int o = 16; o > 0; o >>= 1) {
            v1 += __shfl_xor_sync(0xffffffffu, v1, o);
            v2 += __shfl_xor_sync(0xffffffffu, v2, o);
        }
        if ((tid & 31) == 0) { red1[tid >> 5] = v1; red2[tid >> 5] = v2; }
        __syncthreads();
        if (tid == 0) {
            g_wself[b] = red1[0] + red1[1] + red1[2] + red1[3];
            g_wneigh[b] = red2[0] + red2[1] + red2[2] + red2[3];
        }
        if (tid < 128) {
            float acc = 0.f;
#pragma unroll 8
            for (int t = 0; t < 128; t++) acc += wrow[t] * W1[t * 128 + tid];
            __half h = __float2half_rn(acc);
            bthi[tid * 128 + b] = h;
            btlo[tid * 128 + b] = __float2half_rn(acc - __half2float(h));
        }
    } else {
        int layer = b - 127;  // 1 or 2
        const float* W = (layer == 1) ? W2 : W3;
        __half* oh = bthi + layer * 16384;
        __half* ol = btlo + layer * 16384;
        int tx = tid & 31, ty = tid >> 5;
        for (int ti = 0; ti < 4; ti++)
            for (int tj = 0; tj < 4; tj++) {
                __syncthreads();
#pragma unroll
                for (int it = 0; it < 4; it++)
                    tile[ty + 8 * it][tx] = W[(ti * 32 + ty + 8 * it) * 128 + tj * 32 + tx];
                __syncthreads();
#pragma unroll
                for (int it = 0; it < 4; it++) {
                    int n = tj * 32 + ty + 8 * it, k = ti * 32 + tx;
                    float v = tile[tx][ty + 8 * it];
                    __half h = __float2half_rn(v);
                    oh[n * 128 + k] = h;
                    ol[n * 128 + k] = __float2half_rn(v - __half2float(h));
                }
            }
    }
}

// ---------------- attention: chunked online softmax, 4 blocks/SM ------------------
__global__ void __launch_bounds__(256, 4)
attn_kernel(const float* __restrict__ selfv, const float* __restrict__ neigh,
            const float* __restrict__ eps_p, __half* __restrict__ Xh, int N) {
    int tid = threadIdx.x;
    int wid = tid >> 5, l = tid & 31;
    int n = blockIdx.x * 8 + wid;
    int nn = (n < N) ? n : (N - 1);

    float onepe = 1.0f + eps_p[0];
    float4 ws4 = ((const float4*)g_wself)[l];
    float4 wn4 = ((const float4*)g_wneigh)[l];

    float4 sv = ((const float4*)(selfv + (long)nn * 128))[l];
    const float4* nb = (const float4*)(neigh + (long)nn * 3200);

    float ss = sv.x * ws4.x + sv.y * ws4.y + sv.z * ws4.z + sv.w * ws4.w;
#pragma unroll
    for (int o = 16; o > 0; o >>= 1) ss += __shfl_xor_sync(0xffffffffu, ss, o);

    float4 buf[2][5];
#pragma unroll
    for (int j = 0; j < 5; j++) buf[0][j] = nb[j * 32 + l];

    float m = -1e30f, Z = 0.f;
    float4 acc = make_float4(0.f, 0.f, 0.f, 0.f);

#pragma unroll
    for (int c = 0; c < 5; c++) {
        const int cur = c & 1, nxt = cur ^ 1;
        if (c < 4) {
#pragma unroll
            for (int j = 0; j < 5; j++) buf[nxt][j] = nb[(5 * (c + 1) + j) * 32 + l];
        }
        float p[5];
#pragma unroll
        for (int j = 0; j < 5; j++) {
            float4 v = buf[cur][j];
            p[j] = v.x * wn4.x + v.y * wn4.y + v.z * wn4.z + v.w * wn4.w;
        }
#pragma unroll
        for (int o = 16; o > 0; o >>= 1)
#pragma unroll
            for (int j = 0; j < 5; j++) p[j] += __shfl_xor_sync(0xffffffffu, p[j], o);

        float mc = -1e30f;
#pragma unroll
        for (int j = 0; j < 5; j++) {
            p[j] = leaky(p[j] + ss);
            mc = fmaxf(mc, p[j]);
        }
        if (mc > m) {  // warp-uniform
            float sc = __expf(m - mc);
            Z *= sc;
            acc.x *= sc; acc.y *= sc; acc.z *= sc; acc.w *= sc;
            m = mc;
        }
#pragma unroll
        for (int j = 0; j < 5; j++) {
            float w = __expf(p[j] - m);
            Z += w;
            float4 v = buf[cur][j];
            acc.x += w * v.x; acc.y += w * v.y; acc.z += w * v.z; acc.w += w * v.w;
        }
    }

    float inv = 1.f / Z;
    float x0 = onepe * sv.x + acc.x * inv;
    float x1 = onepe * sv.y + acc.y * inv;
    float x2 = onepe * sv.z + acc.z * inv;
    float x3 = onepe * sv.w + acc.w * inv;
    if (n < N) {
        __half2* dst = (__half2*)(Xh + (long)n * 128);
        dst[2 * l] = __floats2half2_rn(x0, x1);
        dst[2 * l + 1] = __floats2half2_rn(x2, x3);
    }
}

// ---------------- mma.sync GEMM: fp16 two-pass (R11 mainloop), 2 blocks/SM --------
#define A_STRIDE 272
#define SM_BIAS 0
#define SM_CSUM 512
#define SM_CSQ  1024
#define SM_AH   1536
#define SM_BHI  (SM_AH + 128 * A_STRIDE)
#define SM_BLO  (SM_BHI + 128 * A_STRIDE)
#define SM_TOTAL (SM_BLO + 128 * A_STRIDE)

__device__ __forceinline__ void mma16816(float* c, uint32_t a0, uint32_t a1, uint32_t a2,
                                         uint32_t a3, uint32_t b0, uint32_t b1) {
    asm volatile(
        "mma.sync.aligned.m16n8k16.row.col.f32.f16.f16.f32 "
        "{%0,%1,%2,%3}, {%4,%5,%6,%7}, {%8,%9}, {%0,%1,%2,%3};\n"
        : "+f"(c[0]), "+f"(c[1]), "+f"(c[2]), "+f"(c[3])
        : "r"(a0), "r"(a1), "r"(a2), "r"(a3), "r"(b0), "r"(b1));
}

// Two-pass MMA mainloop + stats epilogue (R11-measured best).
__device__ __forceinline__ void gemm_core(char* smem, int tid, float* __restrict__ Y,
                                          float* __restrict__ psum, float* __restrict__ psq,
                                          int row0, int N) {
    int wid = tid >> 5, lane = tid & 31;
    int wm = wid >> 2, wn = wid & 3;
    int g = lane >> 2, t = lane & 3;

    float acc[4][4][4];
#pragma unroll
    for (int mt = 0; mt < 4; mt++)
#pragma unroll
        for (int nt = 0; nt < 4; nt++)
#pragma unroll
            for (int j = 0; j < 4; j++) acc[mt][nt][j] = 0.f;

    const int abase0 = (wm * 64 + g) * A_STRIDE + t * 4;
    const int bbase0 = (wn * 32 + g) * A_STRIDE + t * 4;

#pragma unroll 1
    for (int s = 0; s < 2; s++) {
        const char* Ap = smem + SM_AH + abase0;
        const char* Bp = smem + (s ? SM_BLO : SM_BHI) + bbase0;
#pragma unroll
        for (int ks = 0; ks < 8; ks++) {
            uint32_t a0[4], a1[4], a2[4], a3[4], b0[4], b1[4];
#pragma unroll
            for (int mt = 0; mt < 4; mt++) {
                const char* p = Ap + mt * 16 * A_STRIDE + ks * 32;
                a0[mt] = *(const uint32_t*)(p);
                a1[mt] = *(const uint32_t*)(p + 8 * A_STRIDE);
                a2[mt] = *(const uint32_t*)(p + 16);
                a3[mt] = *(const uint32_t*)(p + 8 * A_STRIDE + 16);
            }
#pragma unroll
            for (int nt = 0; nt < 4; nt++) {
                const char* p = Bp + nt * 8 * A_STRIDE + ks * 32;
                b0[nt] = *(const uint32_t*)(p);
                b1[nt] = *(const uint32_t*)(p + 16);
            }
#pragma unroll
            for (int mt = 0; mt < 4; mt++)
#pragma unroll
                for (int nt = 0; nt < 4; nt++)
                    mma16816(acc[mt][nt], a0[mt], a1[mt], a2[mt], a3[mt], b0[nt], b1[nt]);
        }
    }

    float scol[8], qcol[8];
#pragma unroll
    for (int j = 0; j < 8; j++) { scol[j] = 0.f; qcol[j] = 0.f; }

    const float* bs = (const float*)(smem + SM_BIAS);
#pragma unroll
    for (int nt = 0; nt < 4; nt++) {
        int col = wn * 32 + nt * 8 + 2 * t;
        float bv0 = bs[col], bv1 = bs[col + 1];
#pragma unroll
        for (int mt = 0; mt < 4; mt++) {
            int row = row0 + wm * 64 + mt * 16 + g;
            float c0 = acc[mt][nt][0] + bv0;
            float c1 = acc[mt][nt][1] + bv1;
            float c2 = acc[mt][nt][2] + bv0;
            float c3 = acc[mt][nt][3] + bv1;
            if (row < N) {
                *(float2*)(Y + (long)row * 128 + col) = make_float2(c0, c1);
                scol[nt * 2 + 0] += c0; qcol[nt * 2 + 0] += c0 * c0;
                scol[nt * 2 + 1] += c1; qcol[nt * 2 + 1] += c1 * c1;
            }
            if (row + 8 < N) {
                *(float2*)(Y + (long)(row + 8) * 128 + col) = make_float2(c2, c3);
                scol[nt * 2 + 0] += c2; qcol[nt * 2 + 0] += c2 * c2;
                scol[nt * 2 + 1] += c3; qcol[nt * 2 + 1] += c3 * c3;
            }
        }
    }
#pragma unroll
    for (int j = 0; j < 8; j++) {
#pragma unroll
        for (int o = 4; o < 32; o <<= 1) {
            scol[j] += __shfl_xor_sync(0xffffffffu, scol[j], o);
            qcol[j] += __shfl_xor_sync(0xffffffffu, qcol[j], o);
        }
    }
    if (g == 0) {
        float* cs = (float*)(smem + SM_CSUM);
        float* cq = (float*)(smem + SM_CSQ);
#pragma unroll
        for (int nt = 0; nt < 4; nt++) {
            int col = wn * 32 + nt * 8 + 2 * t;
            atomicAdd(&cs[col], scol[nt * 2 + 0]);
            atomicAdd(&cs[col + 1], scol[nt * 2 + 1]);
            atomicAdd(&cq[col], qcol[nt * 2 + 0]);
            atomicAdd(&cq[col + 1], qcol[nt * 2 + 1]);
        }
    }
    __syncthreads();
    if (tid < 128) {
        atomicAdd(&psum[tid], ((const float*)(smem + SM_CSUM))[tid]);
        atomicAdd(&psq[tid], ((const float*)(smem + SM_CSQ))[tid]);
    }
}

// IN_HALF=true: X is fp16 (attention output), no input BN.
// IN_HALF=false: X is fp32 pre-BN; each thread computes its 4 BN coeffs in
// registers (q = tid&31 constant across its staging rows) -> no barrier before
// A staging; A DRAM loads issue from cycle ~0.
template <bool IN_HALF>
__global__ void __launch_bounds__(256, 2)
gemm_mma(const void* __restrict__ Xv, const __half* __restrict__ bthi,
         const __half* __restrict__ btlo, const float* __restrict__ bias,
         const float* __restrict__ prev_sum, const float* __restrict__ prev_sq,
         const float* __restrict__ gam, const float* __restrict__ bet,
         float* __restrict__ Y, float* __restrict__ psum, float* __restrict__ psq,
         int N) {
    extern __shared__ char smem[];
    int tid = threadIdx.x;
    int row0 = blockIdx.x << 7;

    if (tid < 128) {
        ((float*)(smem + SM_BIAS))[tid] = bias[tid];
        ((float*)(smem + SM_CSUM))[tid] = 0.f;
        ((float*)(smem + SM_CSQ))[tid] = 0.f;
    }

    // ---- stage A (no barrier needed before this) ----
    if (IN_HALF) {
        const __half* Xh = (const __half*)Xv;
#pragma unroll
        for (int it = 0; it < 16; it++) {
            int fi = tid + (it << 8);
            int r = fi >> 5, q = fi & 31;
            int gr = row0 + r;
            uint2 d = make_uint2(0u, 0u);
            if (gr < N) d = ((const uint2*)(Xh + (long)gr * 128))[q];
            int off = r * A_STRIDE + (q << 3);
            *(uint2*)(smem + SM_AH + off) = d;
        }
    } else {
        const float* X = (const float*)Xv;
        int q = tid & 31;
        int kk = q << 2;
        float invN = 1.0f / (float)N;
        float ai[4], ci[4];
#pragma unroll
        for (int j = 0; j < 4; j++) {
            float mean = prev_sum[kk + j] * invN;
            float var = fmaxf(prev_sq[kk + j] * invN - mean * mean, 0.f);
            float a_ = gam[kk + j] * rsqrtf(var + 1e-5f);
            ai[j] = a_;
            ci[j] = bet[kk + j] - a_ * mean;
        }
#pragma unroll
        for (int it = 0; it < 16; it++) {
            int fi = tid + (it << 8);
            int r = fi >> 5;
            int gr = row0 + r;
            float4 v = make_float4(0.f, 0.f, 0.f, 0.f);
            if (gr < N) v = ((const float4*)X)[gr * 32 + q];
            float tt;
            tt = ai[0] * v.x + ci[0]; v.x = leaky(tt);
            tt = ai[1] * v.y + ci[1]; v.y = leaky(tt);
            tt = ai[2] * v.z + ci[2]; v.z = leaky(tt);
            tt = ai[3] * v.w + ci[3]; v.w = leaky(tt);
            __half2 h01 = __floats2half2_rn(v.x, v.y);
            __half2 h23 = __floats2half2_rn(v.z, v.w);
            int off = r * A_STRIDE + (q << 3);
            *(__half2*)(smem + SM_AH + off) = h01;
            *(__half2*)(smem + SM_AH + off + 4) = h23;
        }
    }

    // ---- stage B: precomputed W^T hi/lo fp16 ----
#pragma unroll
    for (int it = 0; it < 8; it++) {
        int fi = tid + (it << 8);
        int n = fi >> 4, c = fi & 15;
        uint4 vh = ((const uint4*)bthi)[fi];
        uint4 vl = ((const uint4*)btlo)[fi];
        int off = n * A_STRIDE + (c << 4);
        *(uint4*)(smem + SM_BHI + off) = vh;
        *(uint4*)(smem + SM_BLO + off) = vl;
    }
    __syncthreads();

    gemm_core(smem, tid, Y, psum, psq, row0, N);
}

// ---------------- final BN + leaky (inline finalize, in place) ----------------
__global__ void epilogue_kernel(float* __restrict__ Y, const float* __restrict__ s,
                                const float* __restrict__ q, const float* __restrict__ gam,
                                const float* __restrict__ bet, int n4, float invN) {
    int i = blockIdx.x * blockDim.x + threadIdx.x;
    if (i < n4) {
        float4 v = ((const float4*)Y)[i];
        int cb = (i & 31) << 2;
        float o[4] = {v.x, v.y, v.z, v.w};
#pragma unroll
        for (int j = 0; j < 4; j++) {
            float mean = s[cb + j] * invN;
            float var = fmaxf(q[cb + j] * invN - mean * mean, 0.f);
            float a_ = gam[cb + j] * rsqrtf(var + 1e-5f);
            float c_ = bet[cb + j] - a_ * mean;
            o[j] = leaky(a_ * o[j] + c_);
        }
        ((float4*)Y)[i] = make_float4(o[0], o[1], o[2], o[3]);
    }
}

// ---------------- launch ----------------
extern "C" void kernel_launch(void* const* d_in, const int* in_sizes, int n_in,
                              void* d_out, int out_size) {
    const float* selfv = (const float*)d_in[0];
    const float* neigh = (const float*)d_in[1];
    const float* Wt    = (const float*)d_in[2];
    const float* aatt  = (const float*)d_in[3];
    const float* eps   = (const float*)d_in[4];
    const float* W1 = (const float*)d_in[5];
    const float* b1 = (const float*)d_in[6];
    const float* g1 = (const float*)d_in[7];
    const float* be1 = (const float*)d_in[8];
    const float* W2 = (const float*)d_in[9];
    const float* b2 = (const float*)d_in[10];
    const float* g2 = (const float*)d_in[11];
    const float* be2 = (const float*)d_in[12];
    const float* W3 = (const float*)d_in[13];
    const float* b3 = (const float*)d_in[14];
    const float* g3 = (const float*)d_in[15];
    const float* be3 = (const float*)d_in[16];
    float* out = (float*)d_out;

    int N = in_sizes[0] / 128;

    float *bufA = nullptr, *bufB = nullptr, *sum = nullptr, *sq = nullptr;
    __half *bufH = nullptr, *bthi = nullptr, *btlo = nullptr;
    cudaGetSymbolAddress((void**)&bufA, g_bufA);
    cudaGetSymbolAddress((void**)&bufB, g_bufB);
    cudaGetSymbolAddress((void**)&bufH, g_bufH);
    cudaGetSymbolAddress((void**)&sum, g_sum);
    cudaGetSymbolAddress((void**)&sq, g_sq);
    cudaGetSymbolAddress((void**)&bthi, g_bthi);
    cudaGetSymbolAddress((void**)&btlo, g_btlo);

    cudaFuncSetAttribute(gemm_mma<true>, cudaFuncAttributeMaxDynamicSharedMemorySize, SM_TOTAL);
    cudaFuncSetAttribute(gemm_mma<false>, cudaFuncAttributeMaxDynamicSharedMemorySize, SM_TOTAL);

    prep_all<<<130, 256>>>(Wt, W1, W2, W3, aatt, bthi, btlo);
    attn_kernel<<<(N + 7) / 8, 256>>>(selfv, neigh, eps, bufH, N);

    int gg = (N + 127) / 128;
    gemm_mma<true><<<gg, 256, SM_TOTAL>>>(bufH, bthi, btlo, b1,
                                          nullptr, nullptr, nullptr, nullptr,
                                          bufB, sum + 0, sq + 0, N);
    gemm_mma<false><<<gg, 256, SM_TOTAL>>>(bufB, bthi + 16384, btlo + 16384, b2,
                                           sum + 0, sq + 0, g1, be1,
                                           bufA, sum + 128, sq + 128, N);
    gemm_mma<false><<<gg, 256, SM_TOTAL>>>(bufA, bthi + 2 * 16384, btlo + 2 * 16384, b3,
                                           sum + 128, sq + 128, g2, be2,
                                           out, sum + 256, sq + 256, N);

    int n4 = N * 32;
    epilogue_kernel<<<(n4 + 255) / 256, 256>>>(out, sum + 256, sq + 256, g3, be3,
                                               n4, 1.0f / (float)N);
}

// round 15
// speedup vs baseline: 1.1952x; 1.0219x over previous
#include <cuda_runtime.h>
#include <cuda_fp16.h>
#include <cstdint>

#define ALPHA 0.2f
#define MAXN 50048

// ---------------- device scratch ----------------
__device__ float g_wself[128];
__device__ float g_wneigh[128];
__device__ __half g_bufH[MAXN * 128];        // attention output (fp16)
__device__ float g_bufA[MAXN * 128];
__device__ float g_bufB[MAXN * 128];
__device__ float g_sum[384];
__device__ float g_sq[384];
__device__ __half g_bt[3 * 16384];           // B^T fp16 per layer, [n][k]

__device__ __forceinline__ float leaky(float x) { return fmaxf(x, ALPHA * x); }

// ---------------- prep_all: one launch for all preprocessing ----------------
__global__ void __launch_bounds__(256)
prep_all(const float* __restrict__ Wt, const float* __restrict__ W1,
         const float* __restrict__ W2, const float* __restrict__ W3,
         const float* __restrict__ a_att, __half* __restrict__ bt) {
    __shared__ float wrow[128];
    __shared__ float red1[8], red2[8];
    __shared__ float tile[32][33];
    int b = blockIdx.x;
    int tid = threadIdx.x;

    if (b < 128) {
        if (tid < 128) wrow[tid] = Wt[b * 128 + tid];
        if (b == 0 && tid < 128) {
            g_sum[tid] = 0.f; g_sum[tid + 128] = 0.f; g_sum[tid + 256] = 0.f;
            g_sq[tid] = 0.f;  g_sq[tid + 128] = 0.f;  g_sq[tid + 256] = 0.f;
        }
        __syncthreads();
        float v1 = 0.f, v2 = 0.f;
        if (tid < 128) {
            v1 = wrow[tid] * a_att[tid];
            v2 = wrow[tid] * a_att[128 + tid];
        }
#pragma unroll
        for (int o = 16; o > 0; o >>= 1) {
            v1 += __shfl_xor_sync(0xffffffffu, v1, o);
            v2 += __shfl_xor_sync(0xffffffffu, v2, o);
        }
        if ((tid & 31) == 0) { red1[tid >> 5] = v1; red2[tid >> 5] = v2; }
        __syncthreads();
        if (tid == 0) {
            g_wself[b] = red1[0] + red1[1] + red1[2] + red1[3];
            g_wneigh[b] = red2[0] + red2[1] + red2[2] + red2[3];
        }
        // bt1[n][k=b] = Wc[b][n] = sum_t Wt[b][t] * W1[t][n]
        if (tid < 128) {
            float acc = 0.f;
#pragma unroll 8
            for (int t = 0; t < 128; t++) acc += wrow[t] * W1[t * 128 + tid];
            bt[tid * 128 + b] = __float2half_rn(acc);
        }
    } else {
        int layer = b - 127;  // 1 or 2
        const float* W = (layer == 1) ? W2 : W3;
        __half* oh = bt + layer * 16384;
        int tx = tid & 31, ty = tid >> 5;
        for (int ti = 0; ti < 4; ti++)
            for (int tj = 0; tj < 4; tj++) {
                __syncthreads();
#pragma unroll
                for (int it = 0; it < 4; it++)
                    tile[ty + 8 * it][tx] = W[(ti * 32 + ty + 8 * it) * 128 + tj * 32 + tx];
                __syncthreads();
#pragma unroll
                for (int it = 0; it < 4; it++) {
                    int n = tj * 32 + ty + 8 * it, k = ti * 32 + tx;
                    oh[n * 128 + k] = __float2half_rn(tile[tx][ty + 8 * it]);
                }
            }
    }
}

// ---------------- attention: chunked online softmax, 4 blocks/SM ------------------
__global__ void __launch_bounds__(256, 4)
attn_kernel(const float* __restrict__ selfv, const float* __restrict__ neigh,
            const float* __restrict__ eps_p, __half* __restrict__ Xh, int N) {
    int tid = threadIdx.x;
    int wid = tid >> 5, l = tid & 31;
    int n = blockIdx.x * 8 + wid;
    int nn = (n < N) ? n : (N - 1);

    float onepe = 1.0f + eps_p[0];
    float4 ws4 = ((const float4*)g_wself)[l];
    float4 wn4 = ((const float4*)g_wneigh)[l];

    float4 sv = ((const float4*)(selfv + (long)nn * 128))[l];
    const float4* nb = (const float4*)(neigh + (long)nn * 3200);

    float ss = sv.x * ws4.x + sv.y * ws4.y + sv.z * ws4.z + sv.w * ws4.w;
#pragma unroll
    for (int o = 16; o > 0; o >>= 1) ss += __shfl_xor_sync(0xffffffffu, ss, o);

    float4 buf[2][5];
#pragma unroll
    for (int j = 0; j < 5; j++) buf[0][j] = nb[j * 32 + l];

    float m = -1e30f, Z = 0.f;
    float4 acc = make_float4(0.f, 0.f, 0.f, 0.f);

#pragma unroll
    for (int c = 0; c < 5; c++) {
        const int cur = c & 1, nxt = cur ^ 1;
        if (c < 4) {
#pragma unroll
            for (int j = 0; j < 5; j++) buf[nxt][j] = nb[(5 * (c + 1) + j) * 32 + l];
        }
        float p[5];
#pragma unroll
        for (int j = 0; j < 5; j++) {
            float4 v = buf[cur][j];
            p[j] = v.x * wn4.x + v.y * wn4.y + v.z * wn4.z + v.w * wn4.w;
        }
#pragma unroll
        for (int o = 16; o > 0; o >>= 1)
#pragma unroll
            for (int j = 0; j < 5; j++) p[j] += __shfl_xor_sync(0xffffffffu, p[j], o);

        float mc = -1e30f;
#pragma unroll
        for (int j = 0; j < 5; j++) {
            p[j] = leaky(p[j] + ss);
            mc = fmaxf(mc, p[j]);
        }
        if (mc > m) {  // warp-uniform
            float sc = __expf(m - mc);
            Z *= sc;
            acc.x *= sc; acc.y *= sc; acc.z *= sc; acc.w *= sc;
            m = mc;
        }
#pragma unroll
        for (int j = 0; j < 5; j++) {
            float w = __expf(p[j] - m);
            Z += w;
            float4 v = buf[cur][j];
            acc.x += w * v.x; acc.y += w * v.y; acc.z += w * v.z; acc.w += w * v.w;
        }
    }

    float inv = 1.f / Z;
    float x0 = onepe * sv.x + acc.x * inv;
    float x1 = onepe * sv.y + acc.y * inv;
    float x2 = onepe * sv.z + acc.z * inv;
    float x3 = onepe * sv.w + acc.w * inv;
    if (n < N) {
        __half2* dst = (__half2*)(Xh + (long)n * 128);
        dst[2 * l] = __floats2half2_rn(x0, x1);
        dst[2 * l + 1] = __floats2half2_rn(x2, x3);
    }
}

// ---------------- mma.sync GEMM: pure fp16 single-pass, 2 blocks/SM ---------------
#define A_STRIDE 272
#define SM_BIAS 0
#define SM_CSUM 512
#define SM_CSQ  1024
#define SM_AH   1536
#define SM_BH   (SM_AH + 128 * A_STRIDE)
#define SM_TOTAL (SM_BH + 128 * A_STRIDE)

__device__ __forceinline__ void mma16816(float* c, uint32_t a0, uint32_t a1, uint32_t a2,
                                         uint32_t a3, uint32_t b0, uint32_t b1) {
    asm volatile(
        "mma.sync.aligned.m16n8k16.row.col.f32.f16.f16.f32 "
        "{%0,%1,%2,%3}, {%4,%5,%6,%7}, {%8,%9}, {%0,%1,%2,%3};\n"
        : "+f"(c[0]), "+f"(c[1]), "+f"(c[2]), "+f"(c[3])
        : "r"(a0), "r"(a1), "r"(a2), "r"(a3), "r"(b0), "r"(b1));
}

// Single-pass MMA mainloop + stats epilogue; expects A/B panels staged.
__device__ __forceinline__ void gemm_core(char* smem, int tid, float* __restrict__ Y,
                                          float* __restrict__ psum, float* __restrict__ psq,
                                          int row0, int N) {
    int wid = tid >> 5, lane = tid & 31;
    int wm = wid >> 2, wn = wid & 3;
    int g = lane >> 2, t = lane & 3;

    float acc[4][4][4];
#pragma unroll
    for (int mt = 0; mt < 4; mt++)
#pragma unroll
        for (int nt = 0; nt < 4; nt++)
#pragma unroll
            for (int j = 0; j < 4; j++) acc[mt][nt][j] = 0.f;

    const char* Ap = smem + SM_AH + (wm * 64 + g) * A_STRIDE + t * 4;
    const char* Bp = smem + SM_BH + (wn * 32 + g) * A_STRIDE + t * 4;

#pragma unroll
    for (int ks = 0; ks < 8; ks++) {
        uint32_t a0[4], a1[4], a2[4], a3[4], b0[4], b1[4];
#pragma unroll
        for (int mt = 0; mt < 4; mt++) {
            const char* p = Ap + mt * 16 * A_STRIDE + ks * 32;
            a0[mt] = *(const uint32_t*)(p);
            a1[mt] = *(const uint32_t*)(p + 8 * A_STRIDE);
            a2[mt] = *(const uint32_t*)(p + 16);
            a3[mt] = *(const uint32_t*)(p + 8 * A_STRIDE + 16);
        }
#pragma unroll
        for (int nt = 0; nt < 4; nt++) {
            const char* p = Bp + nt * 8 * A_STRIDE + ks * 32;
            b0[nt] = *(const uint32_t*)(p);
            b1[nt] = *(const uint32_t*)(p + 16);
        }
#pragma unroll
        for (int mt = 0; mt < 4; mt++)
#pragma unroll
            for (int nt = 0; nt < 4; nt++)
                mma16816(acc[mt][nt], a0[mt], a1[mt], a2[mt], a3[mt], b0[nt], b1[nt]);
    }

    float scol[8], qcol[8];
#pragma unroll
    for (int j = 0; j < 8; j++) { scol[j] = 0.f; qcol[j] = 0.f; }

    const float* bs = (const float*)(smem + SM_BIAS);
#pragma unroll
    for (int nt = 0; nt < 4; nt++) {
        int col = wn * 32 + nt * 8 + 2 * t;
        float bv0 = bs[col], bv1 = bs[col + 1];
#pragma unroll
        for (int mt = 0; mt < 4; mt++) {
            int row = row0 + wm * 64 + mt * 16 + g;
            float c0 = acc[mt][nt][0] + bv0;
            float c1 = acc[mt][nt][1] + bv1;
            float c2 = acc[mt][nt][2] + bv0;
            float c3 = acc[mt][nt][3] + bv1;
            if (row < N) {
                *(float2*)(Y + (long)row * 128 + col) = make_float2(c0, c1);
                scol[nt * 2 + 0] += c0; qcol[nt * 2 + 0] += c0 * c0;
                scol[nt * 2 + 1] += c1; qcol[nt * 2 + 1] += c1 * c1;
            }
            if (row + 8 < N) {
                *(float2*)(Y + (long)(row + 8) * 128 + col) = make_float2(c2, c3);
                scol[nt * 2 + 0] += c2; qcol[nt * 2 + 0] += c2 * c2;
                scol[nt * 2 + 1] += c3; qcol[nt * 2 + 1] += c3 * c3;
            }
        }
    }
#pragma unroll
    for (int j = 0; j < 8; j++) {
#pragma unroll
        for (int o = 4; o < 32; o <<= 1) {
            scol[j] += __shfl_xor_sync(0xffffffffu, scol[j], o);
            qcol[j] += __shfl_xor_sync(0xffffffffu, qcol[j], o);
        }
    }
    if (g == 0) {
        float* cs = (float*)(smem + SM_CSUM);
        float* cq = (float*)(smem + SM_CSQ);
#pragma unroll
        for (int nt = 0; nt < 4; nt++) {
            int col = wn * 32 + nt * 8 + 2 * t;
            atomicAdd(&cs[col], scol[nt * 2 + 0]);
            atomicAdd(&cs[col + 1], scol[nt * 2 + 1]);
            atomicAdd(&cq[col], qcol[nt * 2 + 0]);
            atomicAdd(&cq[col + 1], qcol[nt * 2 + 1]);
        }
    }
    __syncthreads();
    if (tid < 128) {
        atomicAdd(&psum[tid], ((const float*)(smem + SM_CSUM))[tid]);
        atomicAdd(&psq[tid], ((const float*)(smem + SM_CSQ))[tid]);
    }
}

// IN_HALF=true: X is fp16 (attention output), no input BN.
// IN_HALF=false: X is fp32 pre-BN; per-thread register BN coeffs, no pre-barrier.
template <bool IN_HALF>
__global__ void __launch_bounds__(256, 2)
gemm_mma(const void* __restrict__ Xv, const __half* __restrict__ bt,
         const float* __restrict__ bias,
         const float* __restrict__ prev_sum, const float* __restrict__ prev_sq,
         const float* __restrict__ gam, const float* __restrict__ bet,
         float* __restrict__ Y, float* __restrict__ psum, float* __restrict__ psq,
         int N) {
    extern __shared__ char smem[];
    int tid = threadIdx.x;
    int row0 = blockIdx.x << 7;

    if (tid < 128) {
        ((float*)(smem + SM_BIAS))[tid] = bias[tid];
        ((float*)(smem + SM_CSUM))[tid] = 0.f;
        ((float*)(smem + SM_CSQ))[tid] = 0.f;
    }

    // ---- stage A (no barrier needed before this) ----
    if (IN_HALF) {
        const __half* Xh = (const __half*)Xv;
#pragma unroll
        for (int it = 0; it < 16; it++) {
            int fi = tid + (it << 8);
            int r = fi >> 5, q = fi & 31;
            int gr = row0 + r;
            uint2 d = make_uint2(0u, 0u);
            if (gr < N) d = ((const uint2*)(Xh + (long)gr * 128))[q];
            int off = r * A_STRIDE + (q << 3);
            *(uint2*)(smem + SM_AH + off) = d;
        }
    } else {
        const float* X = (const float*)Xv;
        int q = tid & 31;
        int kk = q << 2;
        float invN = 1.0f / (float)N;
        float ai[4], ci[4];
#pragma unroll
        for (int j = 0; j < 4; j++) {
            float mean = prev_sum[kk + j] * invN;
            float var = fmaxf(prev_sq[kk + j] * invN - mean * mean, 0.f);
            float a_ = gam[kk + j] * rsqrtf(var + 1e-5f);
            ai[j] = a_;
            ci[j] = bet[kk + j] - a_ * mean;
        }
#pragma unroll
        for (int it = 0; it < 16; it++) {
            int fi = tid + (it << 8);
            int r = fi >> 5;
            int gr = row0 + r;
            float4 v = make_float4(0.f, 0.f, 0.f, 0.f);
            if (gr < N) v = ((const float4*)X)[gr * 32 + q];
            float tt;
            tt = ai[0] * v.x + ci[0]; v.x = leaky(tt);
            tt = ai[1] * v.y + ci[1]; v.y = leaky(tt);
            tt = ai[2] * v.z + ci[2]; v.z = leaky(tt);
            tt = ai[3] * v.w + ci[3]; v.w = leaky(tt);
            __half2 h01 = __floats2half2_rn(v.x, v.y);
            __half2 h23 = __floats2half2_rn(v.z, v.w);
            int off = r * A_STRIDE + (q << 3);
            *(__half2*)(smem + SM_AH + off) = h01;
            *(__half2*)(smem + SM_AH + off + 4) = h23;
        }
    }

    // ---- stage B: precomputed W^T fp16 (single panel) ----
#pragma unroll
    for (int it = 0; it < 8; it++) {
        int fi = tid + (it << 8);
        int n = fi >> 4, c = fi & 15;
        uint4 vh = ((const uint4*)bt)[fi];
        int off = n * A_STRIDE + (c << 4);
        *(uint4*)(smem + SM_BH + off) = vh;
    }
    __syncthreads();

    gemm_core(smem, tid, Y, psum, psq, row0, N);
}

// ---------------- final BN + leaky (inline finalize, in place) ----------------
__global__ void epilogue_kernel(float* __restrict__ Y, const float* __restrict__ s,
                                const float* __restrict__ q, const float* __restrict__ gam,
                                const float* __restrict__ bet, int n4, float invN) {
    int i = blockIdx.x * blockDim.x + threadIdx.x;
    if (i < n4) {
        float4 v = ((const float4*)Y)[i];
        int cb = (i & 31) << 2;
        float o[4] = {v.x, v.y, v.z, v.w};
#pragma unroll
        for (int j = 0; j < 4; j++) {
            float mean = s[cb + j] * invN;
            float var = fmaxf(q[cb + j] * invN - mean * mean, 0.f);
            float a_ = gam[cb + j] * rsqrtf(var + 1e-5f);
            float c_ = bet[cb + j] - a_ * mean;
            o[j] = leaky(a_ * o[j] + c_);
        }
        ((float4*)Y)[i] = make_float4(o[0], o[1], o[2], o[3]);
    }
}

// ---------------- launch ----------------
extern "C" void kernel_launch(void* const* d_in, const int* in_sizes, int n_in,
                              void* d_out, int out_size) {
    const float* selfv = (const float*)d_in[0];
    const float* neigh = (const float*)d_in[1];
    const float* Wt    = (const float*)d_in[2];
    const float* aatt  = (const float*)d_in[3];
    const float* eps   = (const float*)d_in[4];
    const float* W1 = (const float*)d_in[5];
    const float* b1 = (const float*)d_in[6];
    const float* g1 = (const float*)d_in[7];
    const float* be1 = (const float*)d_in[8];
    const float* W2 = (const float*)d_in[9];
    const float* b2 = (const float*)d_in[10];
    const float* g2 = (const float*)d_in[11];
    const float* be2 = (const float*)d_in[12];
    const float* W3 = (const float*)d_in[13];
    const float* b3 = (const float*)d_in[14];
    const float* g3 = (const float*)d_in[15];
    const float* be3 = (const float*)d_in[16];
    float* out = (float*)d_out;

    int N = in_sizes[0] / 128;

    float *bufA = nullptr, *bufB = nullptr, *sum = nullptr, *sq = nullptr;
    __half *bufH = nullptr, *bt = nullptr;
    cudaGetSymbolAddress((void**)&bufA, g_bufA);
    cudaGetSymbolAddress((void**)&bufB, g_bufB);
    cudaGetSymbolAddress((void**)&bufH, g_bufH);
    cudaGetSymbolAddress((void**)&sum, g_sum);
    cudaGetSymbolAddress((void**)&sq, g_sq);
    cudaGetSymbolAddress((void**)&bt, g_bt);

    cudaFuncSetAttribute(gemm_mma<true>, cudaFuncAttributeMaxDynamicSharedMemorySize, SM_TOTAL);
    cudaFuncSetAttribute(gemm_mma<false>, cudaFuncAttributeMaxDynamicSharedMemorySize, SM_TOTAL);

    prep_all<<<130, 256>>>(Wt, W1, W2, W3, aatt, bt);
    attn_kernel<<<(N + 7) / 8, 256>>>(selfv, neigh, eps, bufH, N);

    int gg = (N + 127) / 128;
    gemm_mma<true><<<gg, 256, SM_TOTAL>>>(bufH, bt, b1,
                                          nullptr, nullptr, nullptr, nullptr,
                                          bufB, sum + 0, sq + 0, N);
    gemm_mma<false><<<gg, 256, SM_TOTAL>>>(bufB, bt + 16384, b2,
                                           sum + 0, sq + 0, g1, be1,
                                           bufA, sum + 128, sq + 128, N);
    gemm_mma<false><<<gg, 256, SM_TOTAL>>>(bufA, bt + 2 * 16384, b3,
                                           sum + 128, sq + 128, g2, be2,
                                           out, sum + 256, sq + 256, N);

    int n4 = N * 32;
    epilogue_kernel<<<(n4 + 255) / 256, 256>>>(out, sum + 256, sq + 256, g3, be3,
                                               n4, 1.0f / (float)N);
}